// round 1
// baseline (speedup 1.0000x reference)
#include <cuda_runtime.h>

// Problem constants
#define Bsz 4
#define Cc 256
#define CE 64
#define Tt 16
#define Hh 56
#define Ww 56
#define HW (Hh*Ww)            // 3136
#define THW (Tt*HW)           // 50176
#define NPOS (Bsz*THW)        // 200704
#define KK 49
#define K2G 196
#define KP 224                // padded corr channels
#define EPS 1e-5f

// Scratch (allocation-free rule: __device__ globals)
__device__ float g_xenc[(size_t)NPOS * CE];   // [b][t][h][w][ce]  (~51 MB)
__device__ float g_corr[(size_t)NPOS * KP];   // [pos][224]        (~180 MB)

// ---------------------------------------------------------------------------
// Kernel 1: encode  — out[p,ce] = relu(bn(sum_c x[b,c,p] * enc_w[ce,c]))
// Tile: 128 positions x 64 ce, K-chunk 16. 256 threads, 8x4 per-thread tile.
// ---------------------------------------------------------------------------
__global__ void k_encode(const float* __restrict__ x, const float* __restrict__ w,
                         const float* __restrict__ gamma, const float* __restrict__ beta,
                         const float* __restrict__ mean, const float* __restrict__ var) {
    __shared__ __align__(16) float As[16][132];  // [c][p]
    __shared__ __align__(16) float Bs[16][68];   // [c][ce]
    const int b  = blockIdx.y;
    const int p0 = blockIdx.x * 128;
    const float* xb = x + (size_t)b * Cc * THW;
    const int tid = threadIdx.x;
    const int px = tid & 15;   // ce dim
    const int py = tid >> 4;   // p dim

    float acc[8][4];
#pragma unroll
    for (int i = 0; i < 8; i++)
#pragma unroll
        for (int j = 0; j < 4; j++) acc[i][j] = 0.f;

    for (int k0 = 0; k0 < Cc; k0 += 16) {
        // A tile: x[b][k0+c][p0+col], contiguous along p -> direct float4
        {
            const int row = tid >> 5;          // 0..7
            const int col = (tid & 31) * 4;    // 0..124
#pragma unroll
            for (int r = 0; r < 16; r += 8) {
                float4 v = *reinterpret_cast<const float4*>(
                    xb + (size_t)(k0 + row + r) * THW + p0 + col);
                *reinterpret_cast<float4*>(&As[row + r][col]) = v;
            }
        }
        // B tile: enc_w[ce][k0+c] -> transposed Bs[c][ce]
        {
            const int ce = tid >> 2;          // 0..63
            const int cl = (tid & 3) * 4;     // 0,4,8,12
            float4 v = *reinterpret_cast<const float4*>(w + ce * Cc + k0 + cl);
            Bs[cl + 0][ce] = v.x; Bs[cl + 1][ce] = v.y;
            Bs[cl + 2][ce] = v.z; Bs[cl + 3][ce] = v.w;
        }
        __syncthreads();
#pragma unroll
        for (int k = 0; k < 16; k++) {
            float4 A0 = *reinterpret_cast<const float4*>(&As[k][py * 4]);
            float4 A1 = *reinterpret_cast<const float4*>(&As[k][64 + py * 4]);
            float4 B0 = *reinterpret_cast<const float4*>(&Bs[k][px * 4]);
            float a[8] = {A0.x, A0.y, A0.z, A0.w, A1.x, A1.y, A1.z, A1.w};
            float bb[4] = {B0.x, B0.y, B0.z, B0.w};
#pragma unroll
            for (int i = 0; i < 8; i++)
#pragma unroll
                for (int j = 0; j < 4; j++) acc[i][j] += a[i] * bb[j];
        }
        __syncthreads();
    }

    // BN(+relu) epilogue; ce = px*4 + j, p = p0 + (i>>2)*64 + py*4 + (i&3)
    float sc[4], bi[4];
#pragma unroll
    for (int j = 0; j < 4; j++) {
        int ce = px * 4 + j;
        sc[j] = gamma[ce] * rsqrtf(var[ce] + EPS);
        bi[j] = beta[ce] - mean[ce] * sc[j];
    }
#pragma unroll
    for (int i = 0; i < 8; i++) {
        int p = p0 + ((i >> 2) * 64) + py * 4 + (i & 3);
        float4 r;
        r.x = fmaxf(acc[i][0] * sc[0] + bi[0], 0.f);
        r.y = fmaxf(acc[i][1] * sc[1] + bi[1], 0.f);
        r.z = fmaxf(acc[i][2] * sc[2] + bi[2], 0.f);
        r.w = fmaxf(acc[i][3] * sc[3] + bi[3], 0.f);
        *reinterpret_cast<float4*>(&g_xenc[((size_t)b * THW + p) * CE + px * 4]) = r;
    }
}

// ---------------------------------------------------------------------------
// Kernel 2: correlation — one warp per (b,t,h,w); 8 warps/block share (b,t,h).
// corr[pos][ko*4+g] = (1/16) * sum_{c in group g} fw[c,t,ko]*x1[c]*x2[c @ offset]
// ---------------------------------------------------------------------------
__global__ void k_corr(const float* __restrict__ fw) {
    __shared__ __align__(16) float fws[KK * CE];   // fws[ko*64 + c]
    __shared__ float res[8][KP];
    const int tid  = threadIdx.x;
    const int warp = tid >> 5;
    const int lane = tid & 31;

    const int pos0 = blockIdx.x * 8;        // 8 | 56, so same (b,t,h) per block
    const int w0 = pos0 % Ww;
    int rest = pos0 / Ww;
    const int h = rest % Hh; rest /= Hh;
    const int t = rest % Tt;
    const int b = rest / Tt;

    // stage filter slice for this t: fw[c][t][ko] -> fws[ko][c]
    for (int idx = tid; idx < KK * CE; idx += 256) {
        int c = idx / KK, ko = idx % KK;
        fws[ko * CE + c] = fw[c * (Tt * KK) + t * KK + ko];
    }
    __syncthreads();

    const int wp = w0 + warp;
    const int t1 = (t == 0) ? 0 : t - 1;
    const float* x1p = g_xenc + (((size_t)(b * Tt + t1) * Hh + h) * Ww + wp) * CE;
    float2 a = *reinterpret_cast<const float2*>(x1p + 2 * lane);
    const float* x2base = g_xenc + ((size_t)(b * Tt + t) * HW) * CE;

    const int g = lane >> 3;           // group of this lane's channels
#pragma unroll 1
    for (int ko = 0; ko < KK; ko++) {
        int ky = ko / 7, kx = ko - ky * 7;
        int y  = h + ky - 3;
        int xx = wp + kx - 3;
        float2 v = make_float2(0.f, 0.f);
        if ((unsigned)y < (unsigned)Hh && (unsigned)xx < (unsigned)Ww)
            v = *reinterpret_cast<const float2*>(x2base + ((size_t)(y * Ww + xx)) * CE + 2 * lane);
        float2 f = *reinterpret_cast<const float2*>(&fws[ko * CE + 2 * lane]);
        float s = f.x * a.x * v.x + f.y * a.y * v.y;
        s += __shfl_xor_sync(0xffffffffu, s, 1);
        s += __shfl_xor_sync(0xffffffffu, s, 2);
        s += __shfl_xor_sync(0xffffffffu, s, 4);
        if ((lane & 7) == 0) res[warp][ko * 4 + g] = s * 0.0625f;
    }
    if (lane < KP - K2G) res[warp][K2G + lane] = 0.f;   // zero pad channels
    __syncwarp();

    float* out = g_corr + (size_t)(pos0 + warp) * KP;
    for (int j = lane; j < KP; j += 32) out[j] = res[warp][j];
}

// ---------------------------------------------------------------------------
// Kernel 3: decode — C[p,o] = sum_j corr[p,j]*dec_w[o,j]; out = relu(x + bn(C))
// Tile 128 p x 128 o, K=224 (zero-padded), 256 threads, 8x8 per-thread.
// ---------------------------------------------------------------------------
__global__ void k_dec(const float* __restrict__ x, const float* __restrict__ dw,
                      const float* __restrict__ gamma, const float* __restrict__ beta,
                      const float* __restrict__ mean, const float* __restrict__ var,
                      float* __restrict__ out) {
    __shared__ __align__(16) float As[16][132];  // [k][p]
    __shared__ __align__(16) float Bs[16][132];  // [k][o]
    const int tid = threadIdx.x;
    const size_t P0 = (size_t)blockIdx.x * 128;
    const int o0 = blockIdx.y * 128;
    const int px = tid & 15;   // p dim
    const int py = tid >> 4;   // o dim

    float acc[8][8];
#pragma unroll
    for (int i = 0; i < 8; i++)
#pragma unroll
        for (int j = 0; j < 8; j++) acc[i][j] = 0.f;

    for (int k0 = 0; k0 < KP; k0 += 16) {
        // A: corr[P0+r][k0+c] -> As[c][r] (transpose)
        {
            const int r = tid >> 1;
            const int c = (tid & 1) * 8;
            const float* src = g_corr + (P0 + r) * KP + k0 + c;
            float4 v0 = *reinterpret_cast<const float4*>(src);
            float4 v1 = *reinterpret_cast<const float4*>(src + 4);
            As[c + 0][r] = v0.x; As[c + 1][r] = v0.y; As[c + 2][r] = v0.z; As[c + 3][r] = v0.w;
            As[c + 4][r] = v1.x; As[c + 5][r] = v1.y; As[c + 6][r] = v1.z; As[c + 7][r] = v1.w;
        }
        // B: dec_w[o0+r][k0+c] (bounds at 196) -> Bs[c][r]
        {
            const int r = tid >> 1;
            const int c = (tid & 1) * 8;
#pragma unroll
            for (int q = 0; q < 8; q += 4) {
                int j = k0 + c + q;
                float4 v = make_float4(0.f, 0.f, 0.f, 0.f);
                if (j < K2G)
                    v = *reinterpret_cast<const float4*>(dw + (size_t)(o0 + r) * K2G + j);
                Bs[c + q + 0][r] = v.x; Bs[c + q + 1][r] = v.y;
                Bs[c + q + 2][r] = v.z; Bs[c + q + 3][r] = v.w;
            }
        }
        __syncthreads();
#pragma unroll
        for (int k = 0; k < 16; k++) {
            float4 A0 = *reinterpret_cast<const float4*>(&As[k][px * 4]);
            float4 A1 = *reinterpret_cast<const float4*>(&As[k][64 + px * 4]);
            float4 B0 = *reinterpret_cast<const float4*>(&Bs[k][py * 4]);
            float4 B1 = *reinterpret_cast<const float4*>(&Bs[k][64 + py * 4]);
            float a[8]  = {A0.x, A0.y, A0.z, A0.w, A1.x, A1.y, A1.z, A1.w};
            float bb[8] = {B0.x, B0.y, B0.z, B0.w, B1.x, B1.y, B1.z, B1.w};
#pragma unroll
            for (int i = 0; i < 8; i++)
#pragma unroll
                for (int j = 0; j < 8; j++) acc[i][j] += a[i] * bb[j];
        }
        __syncthreads();
    }

    // Epilogue: bn + residual + relu. Tiles never straddle batches (50176%128==0).
    const int b   = (int)(P0 / THW);
    const int tp0 = (int)(P0 % THW);
#pragma unroll
    for (int j = 0; j < 8; j++) {
        const int o = o0 + ((j >> 2) * 64) + py * 4 + (j & 3);
        const float sc = gamma[o] * rsqrtf(var[o] + EPS);
        const float bi = beta[o] - mean[o] * sc;
        const float* xrow = x   + ((size_t)b * Cc + o) * THW + tp0;
        float*       orow = out + ((size_t)b * Cc + o) * THW + tp0;
#pragma unroll
        for (int v = 0; v < 2; v++) {
            const int pl = v * 64 + px * 4;
            float4 xr = *reinterpret_cast<const float4*>(xrow + pl);
            float4 r;
            r.x = fmaxf(acc[v * 4 + 0][j] * sc + bi + xr.x, 0.f);
            r.y = fmaxf(acc[v * 4 + 1][j] * sc + bi + xr.y, 0.f);
            r.z = fmaxf(acc[v * 4 + 2][j] * sc + bi + xr.z, 0.f);
            r.w = fmaxf(acc[v * 4 + 3][j] * sc + bi + xr.w, 0.f);
            *reinterpret_cast<float4*>(orow + pl) = r;
        }
    }
}

// ---------------------------------------------------------------------------
extern "C" void kernel_launch(void* const* d_in, const int* in_sizes, int n_in,
                              void* d_out, int out_size) {
    const float* x         = (const float*)d_in[0];
    const float* enc_w     = (const float*)d_in[1];
    const float* enc_gamma = (const float*)d_in[2];
    const float* enc_beta  = (const float*)d_in[3];
    const float* enc_mean  = (const float*)d_in[4];
    const float* enc_var   = (const float*)d_in[5];
    const float* fw        = (const float*)d_in[6];
    const float* dec_w     = (const float*)d_in[7];
    const float* dec_gamma = (const float*)d_in[8];
    const float* dec_beta  = (const float*)d_in[9];
    const float* dec_mean  = (const float*)d_in[10];
    const float* dec_var   = (const float*)d_in[11];
    float* out = (float*)d_out;

    k_encode<<<dim3(THW / 128, Bsz), 256>>>(x, enc_w, enc_gamma, enc_beta, enc_mean, enc_var);
    k_corr<<<NPOS / 8, 256>>>(fw);
    k_dec<<<dim3(NPOS / 128, Cc / 128), 256>>>(x, dec_w, dec_gamma, dec_beta, dec_mean, dec_var, out);
}